// round 5
// baseline (speedup 1.0000x reference)
#include <cuda_runtime.h>
#include <cuda_bf16.h>
#include <mma.h>
#include <math.h>

using namespace nvcuda;

// Problem constants
constexpr int B_ = 8;
constexpr int T_ = 2048;
constexpr int C_ = 1024;
constexpr int M_ROWS = B_ * T_;      // 16384
constexpr int N_QKV  = 3 * C_;       // 3072

// GEMM tiling: 128x128 CTA tile, 8 warps (2Mx4N), warp tile 64x32, BK=32
constexpr int BM = 128;
constexpr int BN = 128;
constexpr int BK = 32;
constexpr int AS_STRIDE = BK + 4;    // 36 floats
constexpr int BN_STRIDE = BN + 4;    // 132 floats
constexpr int A_BUF = BM * AS_STRIDE;            // 4608 floats
constexpr int B_BUF = BM * AS_STRIDE;            // max(128*36, 32*132)=4608
constexpr size_t SMEM_BYTES = (size_t)(2 * A_BUF + 2 * B_BUF) * 4;  // 73728

// Scratch (device globals: allocation-free per harness rules)
__device__ float g_x[(size_t)M_ROWS * C_];        // tf32-rounded x
__device__ float g_wq[(size_t)C_ * N_QKV];        // tf32-rounded Wqkv
__device__ float g_wp[(size_t)C_ * C_];           // tf32-rounded Wproj
__device__ float g_qkv[(size_t)M_ROWS * N_QKV];   // [B*T, 3C] (tf32-rounded)
__device__ float g_S[(size_t)B_ * T_ * T_];       // [B, T, T]
__device__ float g_O[(size_t)M_ROWS * C_];        // [B*T, C] (tf32-rounded)

__device__ __forceinline__ unsigned smem_u32(const void* p) {
    return (unsigned)__cvta_generic_to_shared(p);
}
__device__ __forceinline__ void cp16(unsigned s, const void* g) {
    asm volatile("cp.async.cg.shared.global [%0], [%1], 16;\n" :: "r"(s), "l"(g));
}
__device__ __forceinline__ void cp_commit() {
    asm volatile("cp.async.commit_group;\n" ::: "memory");
}
template <int N>
__device__ __forceinline__ void cp_wait() {
    asm volatile("cp.async.wait_group %0;\n" :: "n"(N) : "memory");
}
__device__ __forceinline__ float round_tf32(float v) {
    return wmma::__float_to_tf32(v);
}

// ---------------------------------------------------------------------------
// Elementwise tf32 rounding of a buffer (float4-vectorized).
// ---------------------------------------------------------------------------
__global__ void __launch_bounds__(256)
round_tf32_kernel(const float* __restrict__ in, float* __restrict__ out, int n4)
{
    int i = blockIdx.x * blockDim.x + threadIdx.x;
    if (i >= n4) return;
    float4 v = ((const float4*)in)[i];
    v.x = round_tf32(v.x);
    v.y = round_tf32(v.y);
    v.z = round_tf32(v.z);
    v.w = round_tf32(v.w);
    ((float4*)out)[i] = v;
}

// ---------------------------------------------------------------------------
// tf32 WMMA GEMM, 128x128x32 tile, 256 threads, cp.async double-buffered.
// Operands must already be tf32-rounded in global memory -> no cvt here.
// C = alpha * A @ B (TRANS_B=0, B is [K,N]) or A @ B^T (TRANS_B=1, B [N,K]).
// CAUSAL: 0 none; 1 skip blocks above diagonal; 2 limit K-loop to m0+BM.
// ROUND_OUT: round epilogue store to tf32 (when C feeds a later GEMM).
// ---------------------------------------------------------------------------
template <bool TRANS_B, int CAUSAL, bool ROUND_OUT>
__global__ void __launch_bounds__(256)
gemm_tf32_kernel(const float* __restrict__ Ag, const float* __restrict__ Bg,
                 float* __restrict__ Cg,
                 int K, int lda, int ldb, int ldc,
                 long long sA, long long sB, long long sC, float alpha)
{
    extern __shared__ float smem[];
    float* As = smem;                 // [2][A_BUF]
    float* Bs = smem + 2 * A_BUF;     // [2][B_BUF]

    const long long bz = blockIdx.z;
    const float* A  = Ag + bz * sA;
    const float* Bp = Bg + bz * sB;
    float*       Cp = Cg + bz * sC;

    const int m0 = blockIdx.y * BM;
    const int n0 = blockIdx.x * BN;

    if (CAUSAL == 1 && n0 > m0 + BM - 1) return;
    int kend = K;
    if (CAUSAL == 2) kend = min(K, m0 + BM);
    const int ntiles = kend / BK;

    const int tid  = threadIdx.x;
    const int warp = tid >> 5;
    const int wm   = (warp >> 2) * 64;   // 2 warp rows (64 each)
    const int wn   = (warp & 3) * 32;    // 4 warp cols (32 each)

    wmma::fragment<wmma::accumulator, 16, 16, 8, float> acc[4][2];
    #pragma unroll
    for (int i = 0; i < 4; i++)
        #pragma unroll
        for (int j = 0; j < 2; j++)
            wmma::fill_fragment(acc[i][j], 0.0f);

    auto stage = [&](int kt, int b) {
        const int kbase = kt * BK;
        // A tile 128x32: 1024 16B-chunks, 4 per thread
        #pragma unroll
        for (int i = tid; i < (BM * BK) / 4; i += 256) {
            int r = i >> 3, c = (i & 7) * 4;
            cp16(smem_u32(&As[b * A_BUF + r * AS_STRIDE + c]),
                 &A[(size_t)(m0 + r) * lda + kbase + c]);
        }
        if constexpr (TRANS_B) {
            // B tile 128x32 from [N,K]
            #pragma unroll
            for (int i = tid; i < (BN * BK) / 4; i += 256) {
                int r = i >> 3, c = (i & 7) * 4;
                cp16(smem_u32(&Bs[b * B_BUF + r * AS_STRIDE + c]),
                     &Bp[(size_t)(n0 + r) * ldb + kbase + c]);
            }
        } else {
            // B tile 32x128 from [K,N]
            #pragma unroll
            for (int i = tid; i < (BK * BN) / 4; i += 256) {
                int r = i >> 5, c = (i & 31) * 4;
                cp16(smem_u32(&Bs[b * B_BUF + r * BN_STRIDE + c]),
                     &Bp[(size_t)(kbase + r) * ldb + n0 + c]);
            }
        }
    };

    stage(0, 0);
    cp_commit();

    for (int kt = 0; kt < ntiles; kt++) {
        const int buf = kt & 1;
        if (kt + 1 < ntiles) {
            stage(kt + 1, (kt + 1) & 1);
            cp_commit();
            cp_wait<1>();
        } else {
            cp_wait<0>();
        }
        __syncthreads();

        #pragma unroll
        for (int kk = 0; kk < BK; kk += 8) {
            wmma::fragment<wmma::matrix_a, 16, 16, 8,
                           wmma::precision::tf32, wmma::row_major> af[4];
            #pragma unroll
            for (int im = 0; im < 4; im++)
                wmma::load_matrix_sync(
                    af[im], &As[buf * A_BUF + (wm + im * 16) * AS_STRIDE + kk],
                    AS_STRIDE);
            if constexpr (TRANS_B) {
                wmma::fragment<wmma::matrix_b, 16, 16, 8,
                               wmma::precision::tf32, wmma::col_major> bf[2];
                #pragma unroll
                for (int in = 0; in < 2; in++)
                    wmma::load_matrix_sync(
                        bf[in],
                        &Bs[buf * B_BUF + (wn + in * 16) * AS_STRIDE + kk],
                        AS_STRIDE);
                #pragma unroll
                for (int im = 0; im < 4; im++)
                    #pragma unroll
                    for (int in = 0; in < 2; in++)
                        wmma::mma_sync(acc[im][in], af[im], bf[in], acc[im][in]);
            } else {
                wmma::fragment<wmma::matrix_b, 16, 16, 8,
                               wmma::precision::tf32, wmma::row_major> bf[2];
                #pragma unroll
                for (int in = 0; in < 2; in++)
                    wmma::load_matrix_sync(
                        bf[in],
                        &Bs[buf * B_BUF + kk * BN_STRIDE + wn + in * 16],
                        BN_STRIDE);
                #pragma unroll
                for (int im = 0; im < 4; im++)
                    #pragma unroll
                    for (int in = 0; in < 2; in++)
                        wmma::mma_sync(acc[im][in], af[im], bf[in], acc[im][in]);
            }
        }
        __syncthreads();
    }

    #pragma unroll
    for (int im = 0; im < 4; im++)
        #pragma unroll
        for (int in = 0; in < 2; in++) {
            #pragma unroll
            for (int t = 0; t < acc[im][in].num_elements; t++) {
                float v = acc[im][in].x[t] * alpha;
                if (ROUND_OUT) v = round_tf32(v);
                acc[im][in].x[t] = v;
            }
            wmma::store_matrix_sync(
                &Cp[(size_t)(m0 + wm + im * 16) * ldc + n0 + wn + in * 16],
                acc[im][in], ldc, wmma::mem_row_major);
        }
}

// ---------------------------------------------------------------------------
// Causal row softmax; output rounded to tf32 (feeds P@V GEMM).
// ---------------------------------------------------------------------------
__device__ __forceinline__ float blockReduce(float v, bool is_max)
{
    __shared__ float sh[33];
    __syncthreads();
    int lane = threadIdx.x & 31, wid = threadIdx.x >> 5;
    #pragma unroll
    for (int o = 16; o; o >>= 1) {
        float u = __shfl_xor_sync(0xFFFFFFFFu, v, o);
        v = is_max ? fmaxf(v, u) : (v + u);
    }
    if (lane == 0) sh[wid] = v;
    __syncthreads();
    if (wid == 0) {
        v = (lane < (blockDim.x >> 5)) ? sh[lane] : (is_max ? -INFINITY : 0.0f);
        #pragma unroll
        for (int o = 16; o; o >>= 1) {
            float u = __shfl_xor_sync(0xFFFFFFFFu, v, o);
            v = is_max ? fmaxf(v, u) : (v + u);
        }
        if (lane == 0) sh[32] = v;
    }
    __syncthreads();
    return sh[32];
}

__global__ void __launch_bounds__(256)
softmax_causal_kernel(float* __restrict__ S)
{
    const int row = blockIdx.x;
    const int i   = row % T_;
    float* Srow = S + (size_t)row * T_;
    const int n = i + 1;

    float m = -INFINITY;
    for (int j = threadIdx.x; j < n; j += blockDim.x)
        m = fmaxf(m, Srow[j]);
    m = blockReduce(m, true);

    float s = 0.0f;
    for (int j = threadIdx.x; j < n; j += blockDim.x) {
        float e = __expf(Srow[j] - m);
        Srow[j] = e;
        s += e;
    }
    s = blockReduce(s, false);
    const float inv = 1.0f / s;

    for (int j = threadIdx.x; j < n; j += blockDim.x)
        Srow[j] = round_tf32(Srow[j] * inv);
    for (int j = n + threadIdx.x; j < T_; j += blockDim.x)
        Srow[j] = 0.0f;
}

// ---------------------------------------------------------------------------
// Launch
// ---------------------------------------------------------------------------
extern "C" void kernel_launch(void* const* d_in, const int* in_sizes, int n_in,
                              void* d_out, int out_size)
{
    const float* x     = (const float*)d_in[0];   // [B, T, C]
    const float* Wqkv  = (const float*)d_in[1];   // [C, 3C]
    const float* Wproj = (const float*)d_in[2];   // [C, C]
    float* out = (float*)d_out;                   // [B, T, C]

    static float *xr = nullptr, *wq = nullptr, *wp = nullptr;
    static float *qkv = nullptr, *S = nullptr, *O = nullptr;
    if (!qkv) {
        cudaGetSymbolAddress((void**)&xr,  g_x);
        cudaGetSymbolAddress((void**)&wq,  g_wq);
        cudaGetSymbolAddress((void**)&wp,  g_wp);
        cudaGetSymbolAddress((void**)&qkv, g_qkv);
        cudaGetSymbolAddress((void**)&S,   g_S);
        cudaGetSymbolAddress((void**)&O,   g_O);
        cudaFuncSetAttribute(gemm_tf32_kernel<false, 0, true>,
            cudaFuncAttributeMaxDynamicSharedMemorySize, (int)SMEM_BYTES);
        cudaFuncSetAttribute(gemm_tf32_kernel<false, 0, false>,
            cudaFuncAttributeMaxDynamicSharedMemorySize, (int)SMEM_BYTES);
        cudaFuncSetAttribute(gemm_tf32_kernel<true, 1, false>,
            cudaFuncAttributeMaxDynamicSharedMemorySize, (int)SMEM_BYTES);
        cudaFuncSetAttribute(gemm_tf32_kernel<false, 2, true>,
            cudaFuncAttributeMaxDynamicSharedMemorySize, (int)SMEM_BYTES);
    }

    const float scale = 1.0f / 32.0f;   // C^-0.5, C=1024
    dim3 blk(256);

    // 0. pre-round operands to tf32
    {
        int n4x = (M_ROWS * C_) / 4;
        round_tf32_kernel<<<(n4x + 255) / 256, 256>>>(x, xr, n4x);
        int n4q = (C_ * N_QKV) / 4;
        round_tf32_kernel<<<(n4q + 255) / 256, 256>>>(Wqkv, wq, n4q);
        int n4p = (C_ * C_) / 4;
        round_tf32_kernel<<<(n4p + 255) / 256, 256>>>(Wproj, wp, n4p);
    }

    // 1. qkv = x @ Wqkv (round output: feeds QK^T and P@V)
    gemm_tf32_kernel<false, 0, true>
        <<<dim3(N_QKV / BN, M_ROWS / BM, 1), blk, SMEM_BYTES>>>(
        xr, wq, qkv, C_, C_, N_QKV, N_QKV, 0, 0, 0, 1.0f);

    // 2. S_b = Q_b @ K_b^T * scale (causal block skip; keep fp32 for softmax)
    gemm_tf32_kernel<true, 1, false>
        <<<dim3(T_ / BN, T_ / BM, B_), blk, SMEM_BYTES>>>(
        qkv, qkv + C_, S, C_, N_QKV, N_QKV, T_,
        (long long)T_ * N_QKV, (long long)T_ * N_QKV, (long long)T_ * T_,
        scale);

    // 3. causal softmax (rounds P to tf32)
    softmax_causal_kernel<<<M_ROWS, 256>>>(S);

    // 4. O_b = P_b @ V_b (K-loop limited; round output for proj GEMM)
    gemm_tf32_kernel<false, 2, true>
        <<<dim3(C_ / BN, T_ / BM, B_), blk, SMEM_BYTES>>>(
        S, qkv + 2 * C_, O, T_, T_, N_QKV, C_,
        (long long)T_ * T_, (long long)T_ * N_QKV, (long long)T_ * C_,
        1.0f);

    // 5. out = O @ Wproj (final: full fp32 store)
    gemm_tf32_kernel<false, 0, false>
        <<<dim3(C_ / BN, M_ROWS / BM, 1), blk, SMEM_BYTES>>>(
        O, wp, out, C_, C_, C_, C_, 0, 0, 0, 1.0f);
}

// round 6
// speedup vs baseline: 1.1286x; 1.1286x over previous
#include <cuda_runtime.h>
#include <cuda_bf16.h>
#include <mma.h>
#include <math.h>

using namespace nvcuda;

// Problem constants
constexpr int B_ = 8;
constexpr int T_ = 2048;
constexpr int C_ = 1024;
constexpr int M_ROWS = B_ * T_;      // 16384
constexpr int N_QKV  = 3 * C_;       // 3072
constexpr int NBLK   = T_ / 64;      // 32 col-blocks per row for partial sums

// GEMM tiling: 128x64 CTA tile, 4 warps (2Mx2N), warp tile 64x32, BK=32
constexpr int BM = 128;
constexpr int BN = 64;
constexpr int BK = 32;
constexpr int AS_STRIDE = BK + 4;    // 36
constexpr int BN_STRIDE = BN + 4;    // 68
constexpr int A_BUF = BM * AS_STRIDE;               // 4608 floats
constexpr int B_BUF = BN * AS_STRIDE;               // 2304 (>= 32*68=2176)
constexpr size_t SMEM_BYTES = (size_t)(2 * A_BUF + 2 * B_BUF) * 4;  // 55296
constexpr int STG_LD = BN + 4;       // 68, stage stride (mult of 4)

// Scratch (device globals)
__device__ float g_x[(size_t)M_ROWS * C_];
__device__ float g_wq[(size_t)C_ * N_QKV];
__device__ float g_wp[(size_t)C_ * C_];
__device__ float g_qkv[(size_t)M_ROWS * N_QKV];
__device__ float g_S[(size_t)B_ * T_ * T_];
__device__ float g_O[(size_t)M_ROWS * C_];
__device__ float g_part[(size_t)M_ROWS * NBLK];   // per (row, colblock) sums
__device__ float g_inv[(size_t)M_ROWS];           // 1 / rowsum

__device__ __forceinline__ unsigned smem_u32(const void* p) {
    return (unsigned)__cvta_generic_to_shared(p);
}
__device__ __forceinline__ void cp16(unsigned s, const void* g) {
    asm volatile("cp.async.cg.shared.global [%0], [%1], 16;\n" :: "r"(s), "l"(g));
}
__device__ __forceinline__ void cp_commit() {
    asm volatile("cp.async.commit_group;\n" ::: "memory");
}
template <int N>
__device__ __forceinline__ void cp_wait() {
    asm volatile("cp.async.wait_group %0;\n" :: "n"(N) : "memory");
}
__device__ __forceinline__ float round_tf32(float v) {
    return wmma::__float_to_tf32(v);
}

// ---------------------------------------------------------------------------
__global__ void __launch_bounds__(256)
round_tf32_kernel(const float* __restrict__ in, float* __restrict__ out, int n4)
{
    int i = blockIdx.x * blockDim.x + threadIdx.x;
    if (i >= n4) return;
    float4 v = ((const float4*)in)[i];
    v.x = round_tf32(v.x); v.y = round_tf32(v.y);
    v.z = round_tf32(v.z); v.w = round_tf32(v.w);
    ((float4*)out)[i] = v;
}

// Deterministic row-sum inversion: inv[g] = 1 / sum_{bx<=i/64} part[g][bx]
__global__ void __launch_bounds__(256)
inv_rowsum_kernel(const float* __restrict__ part, float* __restrict__ inv)
{
    int g = blockIdx.x * blockDim.x + threadIdx.x;
    if (g >= M_ROWS) return;
    int i = g % T_;
    int nb = (i >> 6) + 1;
    float s = 0.0f;
    for (int b = 0; b < nb; b++) s += part[(size_t)g * NBLK + b];
    inv[g] = 1.0f / s;
}

// ---------------------------------------------------------------------------
// tf32 WMMA GEMM, 128x64x32 tile, 128 threads (4 warps, warp tile 64x32),
// cp.async double-buffered. Operands pre-rounded to tf32.
// TRANS_B: B is [N,K] (A@B^T) else [K,N] (A@B).
// CAUSAL: 0 none; 1 skip blocks above diagonal; 2 K-limit to m0+BM.
// EPI: 0 plain; 1 tf32-round; 2 exp+causal-mask+rowsum-partials (QK);
//      3 row-scale by aux[row] + tf32-round (PV).
// ---------------------------------------------------------------------------
template <bool TRANS_B, int CAUSAL, int EPI>
__global__ void __launch_bounds__(128, 4)
gemm_tf32_kernel(const float* __restrict__ Ag, const float* __restrict__ Bg,
                 float* __restrict__ Cg, float* __restrict__ aux,
                 int K, int lda, int ldb, int ldc,
                 long long sA, long long sB, long long sC, float alpha)
{
    extern __shared__ float smem[];
    float* As = smem;                 // [2][A_BUF]
    float* Bs = smem + 2 * A_BUF;     // [2][B_BUF]

    const long long bz = blockIdx.z;
    const float* A  = Ag + bz * sA;
    const float* Bp = Bg + bz * sB;
    float*       Cp = Cg + bz * sC;

    const int m0 = blockIdx.y * BM;
    const int n0 = blockIdx.x * BN;

    if (CAUSAL == 1 && n0 > m0 + BM - 1) return;
    int kend = K;
    if (CAUSAL == 2) kend = min(K, m0 + BM);
    const int ntiles = kend / BK;

    const int tid  = threadIdx.x;
    const int warp = tid >> 5;
    const int lane = tid & 31;
    const int wm   = (warp >> 1) * 64;   // 2 warp rows of 64
    const int wn   = (warp & 1) * 32;    // 2 warp cols of 32

    wmma::fragment<wmma::accumulator, 16, 16, 8, float> acc[4][2];
    #pragma unroll
    for (int i = 0; i < 4; i++)
        #pragma unroll
        for (int j = 0; j < 2; j++)
            wmma::fill_fragment(acc[i][j], 0.0f);

    auto stage = [&](int kt, int b) {
        const int kbase = kt * BK;
        // A tile 128x32: 1024 chunks, 8 per thread
        #pragma unroll
        for (int i = tid; i < (BM * BK) / 4; i += 128) {
            int r = i >> 3, c = (i & 7) * 4;
            cp16(smem_u32(&As[b * A_BUF + r * AS_STRIDE + c]),
                 &A[(size_t)(m0 + r) * lda + kbase + c]);
        }
        if constexpr (TRANS_B) {
            // B tile 64x32 from [N,K]
            #pragma unroll
            for (int i = tid; i < (BN * BK) / 4; i += 128) {
                int r = i >> 3, c = (i & 7) * 4;
                cp16(smem_u32(&Bs[b * B_BUF + r * AS_STRIDE + c]),
                     &Bp[(size_t)(n0 + r) * ldb + kbase + c]);
            }
        } else {
            // B tile 32x64 from [K,N]
            #pragma unroll
            for (int i = tid; i < (BK * BN) / 4; i += 128) {
                int r = i >> 4, c = (i & 15) * 4;
                cp16(smem_u32(&Bs[b * B_BUF + r * BN_STRIDE + c]),
                     &Bp[(size_t)(kbase + r) * ldb + n0 + c]);
            }
        }
    };

    stage(0, 0);
    cp_commit();

    for (int kt = 0; kt < ntiles; kt++) {
        const int buf = kt & 1;
        if (kt + 1 < ntiles) {
            stage(kt + 1, (kt + 1) & 1);
            cp_commit();
            cp_wait<1>();
        } else {
            cp_wait<0>();
        }
        __syncthreads();

        #pragma unroll
        for (int kk = 0; kk < BK; kk += 8) {
            wmma::fragment<wmma::matrix_a, 16, 16, 8,
                           wmma::precision::tf32, wmma::row_major> af[4];
            #pragma unroll
            for (int im = 0; im < 4; im++)
                wmma::load_matrix_sync(
                    af[im], &As[buf * A_BUF + (wm + im * 16) * AS_STRIDE + kk],
                    AS_STRIDE);
            if constexpr (TRANS_B) {
                wmma::fragment<wmma::matrix_b, 16, 16, 8,
                               wmma::precision::tf32, wmma::col_major> bf[2];
                #pragma unroll
                for (int in = 0; in < 2; in++)
                    wmma::load_matrix_sync(
                        bf[in],
                        &Bs[buf * B_BUF + (wn + in * 16) * AS_STRIDE + kk],
                        AS_STRIDE);
                #pragma unroll
                for (int im = 0; im < 4; im++)
                    #pragma unroll
                    for (int in = 0; in < 2; in++)
                        wmma::mma_sync(acc[im][in], af[im], bf[in], acc[im][in]);
            } else {
                wmma::fragment<wmma::matrix_b, 16, 16, 8,
                               wmma::precision::tf32, wmma::row_major> bf[2];
                #pragma unroll
                for (int in = 0; in < 2; in++)
                    wmma::load_matrix_sync(
                        bf[in],
                        &Bs[buf * B_BUF + kk * BN_STRIDE + wn + in * 16],
                        BN_STRIDE);
                #pragma unroll
                for (int im = 0; im < 4; im++)
                    #pragma unroll
                    for (int in = 0; in < 2; in++)
                        wmma::mma_sync(acc[im][in], af[im], bf[in], acc[im][in]);
            }
        }
        __syncthreads();
    }

    // ---- alpha scale on fragments (layout-agnostic) ----
    #pragma unroll
    for (int im = 0; im < 4; im++)
        #pragma unroll
        for (int in = 0; in < 2; in++)
            #pragma unroll
            for (int t = 0; t < acc[im][in].num_elements; t++)
                acc[im][in].x[t] *= alpha;

    if constexpr (EPI <= 1) {
        #pragma unroll
        for (int im = 0; im < 4; im++)
            #pragma unroll
            for (int in = 0; in < 2; in++) {
                if (EPI == 1) {
                    #pragma unroll
                    for (int t = 0; t < acc[im][in].num_elements; t++)
                        acc[im][in].x[t] = round_tf32(acc[im][in].x[t]);
                }
                wmma::store_matrix_sync(
                    &Cp[(size_t)(m0 + wm + im * 16) * ldc + n0 + wn + in * 16],
                    acc[im][in], ldc, wmma::mem_row_major);
            }
    } else {
        // Stage full 128x64 tile in smem (reuses A buffers), then sweep.
        float* stg = smem;   // 128 x STG_LD floats = 34.8KB < 36.8KB A region
        #pragma unroll
        for (int im = 0; im < 4; im++)
            #pragma unroll
            for (int in = 0; in < 2; in++)
                wmma::store_matrix_sync(
                    &stg[(wm + im * 16) * STG_LD + wn + in * 16],
                    acc[im][in], STG_LD, wmma::mem_row_major);
        __syncthreads();

        const int r0 = warp * 32;
        #pragma unroll 4
        for (int rr = 0; rr < 32; rr++) {
            const int r  = r0 + rr;
            const int gi = m0 + r;
            float v0 = stg[r * STG_LD + lane];
            float v1 = stg[r * STG_LD + 32 + lane];
            if constexpr (EPI == 2) {
                const int j0 = n0 + lane, j1 = n0 + 32 + lane;
                float e0 = (j0 <= (gi % T_) + 0) ? __expf(v0) : 0.0f;
                float e1 = (j1 <= (gi % T_) + 0) ? __expf(v1) : 0.0f;
                // NOTE: per-batch row index == gi within batch since Cp/A are
                // batch-sliced; row index in S is r+m0 which IS the in-batch
                // row (bz handled by pointer offset). gi%T_ == gi here (m0<T).
                e0 = round_tf32(e0);
                e1 = round_tf32(e1);
                float s = e0 + e1;
                #pragma unroll
                for (int o = 16; o; o >>= 1)
                    s += __shfl_xor_sync(0xFFFFFFFFu, s, o);
                if (lane == 0)
                    aux[(bz * T_ + gi) * NBLK + blockIdx.x] = s;
                Cp[(size_t)gi * ldc + j0] = e0;
                Cp[(size_t)gi * ldc + j1] = e1;
            } else {  // EPI == 3: row scale + round
                float sc = aux[bz * T_ + gi];
                Cp[(size_t)gi * ldc + n0 + lane]      = round_tf32(v0 * sc);
                Cp[(size_t)gi * ldc + n0 + 32 + lane] = round_tf32(v1 * sc);
            }
        }
    }
}

// ---------------------------------------------------------------------------
// Launch
// ---------------------------------------------------------------------------
extern "C" void kernel_launch(void* const* d_in, const int* in_sizes, int n_in,
                              void* d_out, int out_size)
{
    const float* x     = (const float*)d_in[0];   // [B, T, C]
    const float* Wqkv  = (const float*)d_in[1];   // [C, 3C]
    const float* Wproj = (const float*)d_in[2];   // [C, C]
    float* out = (float*)d_out;                   // [B, T, C]

    static float *xr = nullptr, *wq = nullptr, *wp = nullptr;
    static float *qkv = nullptr, *S = nullptr, *O = nullptr;
    static float *part = nullptr, *inv = nullptr;
    if (!qkv) {
        cudaGetSymbolAddress((void**)&xr,   g_x);
        cudaGetSymbolAddress((void**)&wq,   g_wq);
        cudaGetSymbolAddress((void**)&wp,   g_wp);
        cudaGetSymbolAddress((void**)&qkv,  g_qkv);
        cudaGetSymbolAddress((void**)&S,    g_S);
        cudaGetSymbolAddress((void**)&O,    g_O);
        cudaGetSymbolAddress((void**)&part, g_part);
        cudaGetSymbolAddress((void**)&inv,  g_inv);
        cudaFuncSetAttribute(gemm_tf32_kernel<false, 0, 1>,
            cudaFuncAttributeMaxDynamicSharedMemorySize, (int)SMEM_BYTES);
        cudaFuncSetAttribute(gemm_tf32_kernel<true, 1, 2>,
            cudaFuncAttributeMaxDynamicSharedMemorySize, (int)SMEM_BYTES);
        cudaFuncSetAttribute(gemm_tf32_kernel<false, 2, 3>,
            cudaFuncAttributeMaxDynamicSharedMemorySize, (int)SMEM_BYTES);
        cudaFuncSetAttribute(gemm_tf32_kernel<false, 0, 0>,
            cudaFuncAttributeMaxDynamicSharedMemorySize, (int)SMEM_BYTES);
    }

    const float scale = 1.0f / 32.0f;   // C^-0.5
    dim3 blk(128);

    // 0. pre-round operands to tf32
    {
        int n4x = (M_ROWS * C_) / 4;
        round_tf32_kernel<<<(n4x + 255) / 256, 256>>>(x, xr, n4x);
        int n4q = (C_ * N_QKV) / 4;
        round_tf32_kernel<<<(n4q + 255) / 256, 256>>>(Wqkv, wq, n4q);
        int n4p = (C_ * C_) / 4;
        round_tf32_kernel<<<(n4p + 255) / 256, 256>>>(Wproj, wp, n4p);
    }

    // 1. qkv = x @ Wqkv (tf32-rounded output)
    gemm_tf32_kernel<false, 0, 1>
        <<<dim3(N_QKV / BN, M_ROWS / BM, 1), blk, SMEM_BYTES>>>(
        xr, wq, qkv, nullptr, C_, C_, N_QKV, N_QKV, 0, 0, 0, 1.0f);

    // 2. E_b = exp(scale * Q_b @ K_b^T) with causal mask; writes partial
    //    row sums (deterministic, per col-block). Softmax kernel eliminated.
    gemm_tf32_kernel<true, 1, 2>
        <<<dim3(T_ / BN, T_ / BM, B_), blk, SMEM_BYTES>>>(
        qkv, qkv + C_, S, part, C_, N_QKV, N_QKV, T_,
        (long long)T_ * N_QKV, (long long)T_ * N_QKV, (long long)T_ * T_,
        scale);

    // 3. inv[row] = 1 / rowsum
    inv_rowsum_kernel<<<(M_ROWS + 255) / 256, 256>>>(part, inv);

    // 4. O_b = diag(inv) * E_b @ V_b (K-limited; row-scaled, rounded)
    gemm_tf32_kernel<false, 2, 3>
        <<<dim3(C_ / BN, T_ / BM, B_), blk, SMEM_BYTES>>>(
        S, qkv + 2 * C_, O, inv, T_, T_, N_QKV, C_,
        (long long)T_ * T_, (long long)T_ * N_QKV, (long long)T_ * C_,
        1.0f);

    // 5. out = O @ Wproj (final fp32)
    gemm_tf32_kernel<false, 0, 0>
        <<<dim3(C_ / BN, M_ROWS / BM, 1), blk, SMEM_BYTES>>>(
        O, wp, out, nullptr, C_, C_, C_, C_, 0, 0, 0, 1.0f);
}

// round 7
// speedup vs baseline: 1.1491x; 1.0181x over previous
#include <cuda_runtime.h>
#include <cuda_bf16.h>
#include <mma.h>
#include <math.h>

using namespace nvcuda;

// Problem constants
constexpr int B_ = 8;
constexpr int T_ = 2048;
constexpr int C_ = 1024;
constexpr int M_ROWS = B_ * T_;      // 16384
constexpr int N_QKV  = 3 * C_;       // 3072
constexpr int NBLK   = T_ / 64;      // 32 col-blocks per row for partial sums

// GEMM tiling: 128x64 CTA tile, 4 warps (2Mx2N), warp tile 64x32, BK=32
constexpr int BM = 128;
constexpr int BN = 64;
constexpr int BK = 32;
constexpr int AS_STRIDE = BK + 4;    // 36
constexpr int BN_STRIDE = BN + 4;    // 68
constexpr int A_BUF = BM * AS_STRIDE;               // 4608 floats
constexpr int B_BUF = BN * AS_STRIDE;               // 2304 (>= 32*68=2176)
constexpr size_t SMEM_BYTES = (size_t)(2 * A_BUF + 2 * B_BUF) * 4;  // 55296
constexpr int STG_LD = BN + 4;       // 68, stage stride

// Scratch (device globals)
__device__ float g_x[(size_t)M_ROWS * C_];
__device__ float g_wq[(size_t)C_ * N_QKV];
__device__ float g_wp[(size_t)C_ * C_];
__device__ float g_qkv[(size_t)M_ROWS * N_QKV];
__device__ float g_S[(size_t)B_ * T_ * T_];
__device__ float g_O[(size_t)M_ROWS * C_];
__device__ float g_part[(size_t)M_ROWS * NBLK];   // per (row, colblock) sums
__device__ float g_inv[(size_t)M_ROWS];           // 1 / rowsum

__device__ __forceinline__ unsigned smem_u32(const void* p) {
    return (unsigned)__cvta_generic_to_shared(p);
}
__device__ __forceinline__ void cp16(unsigned s, const void* g) {
    asm volatile("cp.async.cg.shared.global [%0], [%1], 16;\n" :: "r"(s), "l"(g));
}
__device__ __forceinline__ void cp_commit() {
    asm volatile("cp.async.commit_group;\n" ::: "memory");
}
template <int N>
__device__ __forceinline__ void cp_wait() {
    asm volatile("cp.async.wait_group %0;\n" :: "n"(N) : "memory");
}
__device__ __forceinline__ float round_tf32(float v) {
    return wmma::__float_to_tf32(v);
}

// ---------------------------------------------------------------------------
__global__ void __launch_bounds__(256)
round_tf32_kernel(const float* __restrict__ in, float* __restrict__ out, int n4)
{
    int i = blockIdx.x * blockDim.x + threadIdx.x;
    if (i >= n4) return;
    float4 v = ((const float4*)in)[i];
    v.x = round_tf32(v.x); v.y = round_tf32(v.y);
    v.z = round_tf32(v.z); v.w = round_tf32(v.w);
    ((float4*)out)[i] = v;
}

// Deterministic row-sum inversion: inv[g] = 1 / sum_{bx<=i/64} part[g][bx]
__global__ void __launch_bounds__(256)
inv_rowsum_kernel(const float* __restrict__ part, float* __restrict__ inv)
{
    int g = blockIdx.x * blockDim.x + threadIdx.x;
    if (g >= M_ROWS) return;
    int i = g % T_;
    int nb = (i >> 6) + 1;
    float s = 0.0f;
    for (int b = 0; b < nb; b++) s += part[(size_t)g * NBLK + b];
    inv[g] = 1.0f / s;
}

// ---------------------------------------------------------------------------
// tf32 WMMA GEMM, 128x64x32 tile, 128 threads (4 warps, warp tile 64x32),
// cp.async double-buffered global staging + double-buffered FRAGMENTS in the
// kk loop (software pipeline hides LDS latency behind the MMA batch).
// TRANS_B: B is [N,K] (A@B^T) else [K,N] (A@B).
// CAUSAL: 0 none; 1 skip blocks above diagonal; 2 K-limit to m0+BM.
// EPI: 0 plain; 1 tf32-round; 2 exp+causal-mask+rowsum-partials (QK);
//      3 row-scale by aux[row] + tf32-round (PV).
// ---------------------------------------------------------------------------
template <bool TRANS_B, int CAUSAL, int EPI>
__global__ void __launch_bounds__(128, 3)
gemm_tf32_kernel(const float* __restrict__ Ag, const float* __restrict__ Bg,
                 float* __restrict__ Cg, float* __restrict__ aux,
                 int K, int lda, int ldb, int ldc,
                 long long sA, long long sB, long long sC, float alpha)
{
    extern __shared__ float smem[];
    float* As = smem;                 // [2][A_BUF]
    float* Bs = smem + 2 * A_BUF;     // [2][B_BUF]

    const long long bz = blockIdx.z;
    const float* A  = Ag + bz * sA;
    const float* Bp = Bg + bz * sB;
    float*       Cp = Cg + bz * sC;

    const int m0 = blockIdx.y * BM;
    const int n0 = blockIdx.x * BN;

    if (CAUSAL == 1 && n0 > m0 + BM - 1) return;
    int kend = K;
    if (CAUSAL == 2) kend = min(K, m0 + BM);
    const int ntiles = kend / BK;

    const int tid  = threadIdx.x;
    const int warp = tid >> 5;
    const int lane = tid & 31;
    const int wm   = (warp >> 1) * 64;   // 2 warp rows of 64
    const int wn   = (warp & 1) * 32;    // 2 warp cols of 32

    wmma::fragment<wmma::accumulator, 16, 16, 8, float> acc[4][2];
    #pragma unroll
    for (int i = 0; i < 4; i++)
        #pragma unroll
        for (int j = 0; j < 2; j++)
            wmma::fill_fragment(acc[i][j], 0.0f);

    auto stage = [&](int kt, int b) {
        const int kbase = kt * BK;
        #pragma unroll
        for (int i = tid; i < (BM * BK) / 4; i += 128) {
            int r = i >> 3, c = (i & 7) * 4;
            cp16(smem_u32(&As[b * A_BUF + r * AS_STRIDE + c]),
                 &A[(size_t)(m0 + r) * lda + kbase + c]);
        }
        if constexpr (TRANS_B) {
            #pragma unroll
            for (int i = tid; i < (BN * BK) / 4; i += 128) {
                int r = i >> 3, c = (i & 7) * 4;
                cp16(smem_u32(&Bs[b * B_BUF + r * AS_STRIDE + c]),
                     &Bp[(size_t)(n0 + r) * ldb + kbase + c]);
            }
        } else {
            #pragma unroll
            for (int i = tid; i < (BK * BN) / 4; i += 128) {
                int r = i >> 4, c = (i & 15) * 4;
                cp16(smem_u32(&Bs[b * B_BUF + r * BN_STRIDE + c]),
                     &Bp[(size_t)(kbase + r) * ldb + n0 + c]);
            }
        }
    };

    stage(0, 0);
    cp_commit();

    using FragA = wmma::fragment<wmma::matrix_a, 16, 16, 8,
                                 wmma::precision::tf32, wmma::row_major>;

    for (int kt = 0; kt < ntiles; kt++) {
        const int buf = kt & 1;
        if (kt + 1 < ntiles) {
            stage(kt + 1, (kt + 1) & 1);
            cp_commit();
            cp_wait<1>();
        } else {
            cp_wait<0>();
        }
        __syncthreads();

        const float* Abase = &As[buf * A_BUF];
        const float* Bbase = &Bs[buf * B_BUF];

        if constexpr (TRANS_B) {
            using FragB = wmma::fragment<wmma::matrix_b, 16, 16, 8,
                                         wmma::precision::tf32, wmma::col_major>;
            FragA af[2][4];
            FragB bf[2][2];
            auto loadf = [&](int pb, int kk) {
                #pragma unroll
                for (int im = 0; im < 4; im++)
                    wmma::load_matrix_sync(af[pb][im],
                        &Abase[(wm + im * 16) * AS_STRIDE + kk], AS_STRIDE);
                #pragma unroll
                for (int in = 0; in < 2; in++)
                    wmma::load_matrix_sync(bf[pb][in],
                        &Bbase[(wn + in * 16) * AS_STRIDE + kk], AS_STRIDE);
            };
            loadf(0, 0);
            #pragma unroll
            for (int ki = 0; ki < BK / 8; ki++) {
                const int cur = ki & 1;
                if (ki + 1 < BK / 8) loadf(cur ^ 1, (ki + 1) * 8);
                #pragma unroll
                for (int im = 0; im < 4; im++)
                    #pragma unroll
                    for (int in = 0; in < 2; in++)
                        wmma::mma_sync(acc[im][in], af[cur][im], bf[cur][in],
                                       acc[im][in]);
            }
        } else {
            using FragB = wmma::fragment<wmma::matrix_b, 16, 16, 8,
                                         wmma::precision::tf32, wmma::row_major>;
            FragA af[2][4];
            FragB bf[2][2];
            auto loadf = [&](int pb, int kk) {
                #pragma unroll
                for (int im = 0; im < 4; im++)
                    wmma::load_matrix_sync(af[pb][im],
                        &Abase[(wm + im * 16) * AS_STRIDE + kk], AS_STRIDE);
                #pragma unroll
                for (int in = 0; in < 2; in++)
                    wmma::load_matrix_sync(bf[pb][in],
                        &Bbase[kk * BN_STRIDE + wn + in * 16], BN_STRIDE);
            };
            loadf(0, 0);
            #pragma unroll
            for (int ki = 0; ki < BK / 8; ki++) {
                const int cur = ki & 1;
                if (ki + 1 < BK / 8) loadf(cur ^ 1, (ki + 1) * 8);
                #pragma unroll
                for (int im = 0; im < 4; im++)
                    #pragma unroll
                    for (int in = 0; in < 2; in++)
                        wmma::mma_sync(acc[im][in], af[cur][im], bf[cur][in],
                                       acc[im][in]);
            }
        }
        __syncthreads();
    }

    // ---- alpha scale on fragments ----
    #pragma unroll
    for (int im = 0; im < 4; im++)
        #pragma unroll
        for (int in = 0; in < 2; in++)
            #pragma unroll
            for (int t = 0; t < acc[im][in].num_elements; t++)
                acc[im][in].x[t] *= alpha;

    if constexpr (EPI <= 1) {
        #pragma unroll
        for (int im = 0; im < 4; im++)
            #pragma unroll
            for (int in = 0; in < 2; in++) {
                if (EPI == 1) {
                    #pragma unroll
                    for (int t = 0; t < acc[im][in].num_elements; t++)
                        acc[im][in].x[t] = round_tf32(acc[im][in].x[t]);
                }
                wmma::store_matrix_sync(
                    &Cp[(size_t)(m0 + wm + im * 16) * ldc + n0 + wn + in * 16],
                    acc[im][in], ldc, wmma::mem_row_major);
            }
    } else {
        // Stage full 128x64 tile in smem (reuses A buffers), then sweep.
        float* stg = smem;   // 128 x STG_LD floats
        #pragma unroll
        for (int im = 0; im < 4; im++)
            #pragma unroll
            for (int in = 0; in < 2; in++)
                wmma::store_matrix_sync(
                    &stg[(wm + im * 16) * STG_LD + wn + in * 16],
                    acc[im][in], STG_LD, wmma::mem_row_major);
        __syncthreads();

        const int r0 = warp * 32;
        #pragma unroll 4
        for (int rr = 0; rr < 32; rr++) {
            const int r  = r0 + rr;
            const int gi = m0 + r;              // in-batch row (m0 < T)
            float v0 = stg[r * STG_LD + lane];
            float v1 = stg[r * STG_LD + 32 + lane];
            if constexpr (EPI == 2) {
                const int j0 = n0 + lane, j1 = n0 + 32 + lane;
                float e0 = (j0 <= gi) ? __expf(v0) : 0.0f;
                float e1 = (j1 <= gi) ? __expf(v1) : 0.0f;
                e0 = round_tf32(e0);
                e1 = round_tf32(e1);
                float s = e0 + e1;
                #pragma unroll
                for (int o = 16; o; o >>= 1)
                    s += __shfl_xor_sync(0xFFFFFFFFu, s, o);
                if (lane == 0)
                    aux[(bz * T_ + gi) * NBLK + blockIdx.x] = s;
                Cp[(size_t)gi * ldc + j0] = e0;
                Cp[(size_t)gi * ldc + j1] = e1;
            } else {  // EPI == 3: row scale + round
                float sc = aux[bz * T_ + gi];
                Cp[(size_t)gi * ldc + n0 + lane]      = round_tf32(v0 * sc);
                Cp[(size_t)gi * ldc + n0 + 32 + lane] = round_tf32(v1 * sc);
            }
        }
    }
}

// ---------------------------------------------------------------------------
// Launch
// ---------------------------------------------------------------------------
extern "C" void kernel_launch(void* const* d_in, const int* in_sizes, int n_in,
                              void* d_out, int out_size)
{
    const float* x     = (const float*)d_in[0];   // [B, T, C]
    const float* Wqkv  = (const float*)d_in[1];   // [C, 3C]
    const float* Wproj = (const float*)d_in[2];   // [C, C]
    float* out = (float*)d_out;                   // [B, T, C]

    static float *xr = nullptr, *wq = nullptr, *wp = nullptr;
    static float *qkv = nullptr, *S = nullptr, *O = nullptr;
    static float *part = nullptr, *inv = nullptr;
    if (!qkv) {
        cudaGetSymbolAddress((void**)&xr,   g_x);
        cudaGetSymbolAddress((void**)&wq,   g_wq);
        cudaGetSymbolAddress((void**)&wp,   g_wp);
        cudaGetSymbolAddress((void**)&qkv,  g_qkv);
        cudaGetSymbolAddress((void**)&S,    g_S);
        cudaGetSymbolAddress((void**)&O,    g_O);
        cudaGetSymbolAddress((void**)&part, g_part);
        cudaGetSymbolAddress((void**)&inv,  g_inv);
        cudaFuncSetAttribute(gemm_tf32_kernel<false, 0, 1>,
            cudaFuncAttributeMaxDynamicSharedMemorySize, (int)SMEM_BYTES);
        cudaFuncSetAttribute(gemm_tf32_kernel<true, 1, 2>,
            cudaFuncAttributeMaxDynamicSharedMemorySize, (int)SMEM_BYTES);
        cudaFuncSetAttribute(gemm_tf32_kernel<false, 2, 3>,
            cudaFuncAttributeMaxDynamicSharedMemorySize, (int)SMEM_BYTES);
        cudaFuncSetAttribute(gemm_tf32_kernel<false, 0, 0>,
            cudaFuncAttributeMaxDynamicSharedMemorySize, (int)SMEM_BYTES);
    }

    const float scale = 1.0f / 32.0f;   // C^-0.5
    dim3 blk(128);

    // 0. pre-round operands to tf32
    {
        int n4x = (M_ROWS * C_) / 4;
        round_tf32_kernel<<<(n4x + 255) / 256, 256>>>(x, xr, n4x);
        int n4q = (C_ * N_QKV) / 4;
        round_tf32_kernel<<<(n4q + 255) / 256, 256>>>(Wqkv, wq, n4q);
        int n4p = (C_ * C_) / 4;
        round_tf32_kernel<<<(n4p + 255) / 256, 256>>>(Wproj, wp, n4p);
    }

    // 1. qkv = x @ Wqkv (tf32-rounded output)
    gemm_tf32_kernel<false, 0, 1>
        <<<dim3(N_QKV / BN, M_ROWS / BM, 1), blk, SMEM_BYTES>>>(
        xr, wq, qkv, nullptr, C_, C_, N_QKV, N_QKV, 0, 0, 0, 1.0f);

    // 2. E_b = exp(scale * Q_b @ K_b^T) causal-masked; partial row sums.
    gemm_tf32_kernel<true, 1, 2>
        <<<dim3(T_ / BN, T_ / BM, B_), blk, SMEM_BYTES>>>(
        qkv, qkv + C_, S, part, C_, N_QKV, N_QKV, T_,
        (long long)T_ * N_QKV, (long long)T_ * N_QKV, (long long)T_ * T_,
        scale);

    // 3. inv[row] = 1 / rowsum
    inv_rowsum_kernel<<<(M_ROWS + 255) / 256, 256>>>(part, inv);

    // 4. O_b = diag(inv) * E_b @ V_b (K-limited; row-scaled, rounded)
    gemm_tf32_kernel<false, 2, 3>
        <<<dim3(C_ / BN, T_ / BM, B_), blk, SMEM_BYTES>>>(
        S, qkv + 2 * C_, O, inv, T_, T_, N_QKV, C_,
        (long long)T_ * T_, (long long)T_ * N_QKV, (long long)T_ * C_,
        1.0f);

    // 5. out = O @ Wproj (final fp32)
    gemm_tf32_kernel<false, 0, 0>
        <<<dim3(C_ / BN, M_ROWS / BM, 1), blk, SMEM_BYTES>>>(
        O, wp, out, nullptr, C_, C_, C_, C_, 0, 0, 0, 1.0f);
}

// round 8
// speedup vs baseline: 1.2018x; 1.0459x over previous
#include <cuda_runtime.h>
#include <cuda_bf16.h>
#include <mma.h>
#include <math.h>

using namespace nvcuda;

// Problem constants
constexpr int B_ = 8;
constexpr int T_ = 2048;
constexpr int C_ = 1024;
constexpr int M_ROWS = B_ * T_;      // 16384
constexpr int N_QKV  = 3 * C_;       // 3072
constexpr int NBLK   = T_ / 128;     // 16 col-blocks per row for partial sums

// GEMM tiling: 128x128 CTA tile, 4 warps (2Mx2N), warp tile 64x64, BK=32
constexpr int BM = 128;
constexpr int BN = 128;
constexpr int BK = 32;
constexpr int AS_STRIDE = BK + 4;    // 36
constexpr int BN_STRIDE = BN + 4;    // 132
constexpr int A_BUF = BM * AS_STRIDE;               // 4608 floats
constexpr int B_BUF = BM * AS_STRIDE;               // 4608 (>= 32*132=4224)
constexpr size_t SMEM_BYTES = (size_t)(2 * A_BUF + 2 * B_BUF) * 4;  // 73728
constexpr int STG_LD = BN + 4;       // 132, stage stride

// Scratch (device globals)
__device__ float g_x[(size_t)M_ROWS * C_];
__device__ float g_wq[(size_t)C_ * N_QKV];
__device__ float g_wp[(size_t)C_ * C_];
__device__ float g_qkv[(size_t)M_ROWS * N_QKV];
__device__ float g_S[(size_t)B_ * T_ * T_];
__device__ float g_O[(size_t)M_ROWS * C_];
__device__ float g_part[(size_t)M_ROWS * NBLK];   // per (row, colblock) sums
__device__ float g_inv[(size_t)M_ROWS];           // 1 / rowsum

__device__ __forceinline__ unsigned smem_u32(const void* p) {
    return (unsigned)__cvta_generic_to_shared(p);
}
__device__ __forceinline__ void cp16(unsigned s, const void* g) {
    asm volatile("cp.async.cg.shared.global [%0], [%1], 16;\n" :: "r"(s), "l"(g));
}
__device__ __forceinline__ void cp_commit() {
    asm volatile("cp.async.commit_group;\n" ::: "memory");
}
template <int N>
__device__ __forceinline__ void cp_wait() {
    asm volatile("cp.async.wait_group %0;\n" :: "n"(N) : "memory");
}
__device__ __forceinline__ float round_tf32(float v) {
    return wmma::__float_to_tf32(v);
}

// ---------------------------------------------------------------------------
__global__ void __launch_bounds__(256)
round_tf32_kernel(const float* __restrict__ in, float* __restrict__ out, int n4)
{
    int i = blockIdx.x * blockDim.x + threadIdx.x;
    if (i >= n4) return;
    float4 v = ((const float4*)in)[i];
    v.x = round_tf32(v.x); v.y = round_tf32(v.y);
    v.z = round_tf32(v.z); v.w = round_tf32(v.w);
    ((float4*)out)[i] = v;
}

// Deterministic row-sum inversion: inv[g] = 1 / sum_{bx<=i/128} part[g][bx]
__global__ void __launch_bounds__(256)
inv_rowsum_kernel(const float* __restrict__ part, float* __restrict__ inv)
{
    int g = blockIdx.x * blockDim.x + threadIdx.x;
    if (g >= M_ROWS) return;
    int i = g % T_;
    int nb = (i >> 7) + 1;
    float s = 0.0f;
    for (int b = 0; b < nb; b++) s += part[(size_t)g * NBLK + b];
    inv[g] = 1.0f / s;
}

// ---------------------------------------------------------------------------
// tf32 WMMA GEMM, 128x128x32 tile, 128 threads (4 warps, warp tile 64x64),
// cp.async double-buffered staging. Operands pre-rounded to tf32.
// TRANS_B: B is [N,K] (A@B^T) else [K,N] (A@B).
// CAUSAL: 0 none; 1 skip blocks above diagonal; 2 K-limit to m0+BM.
// EPI: 0 plain; 1 tf32-round; 2 exp+causal-mask+rowsum-partials (QK);
//      3 row-scale by aux[row] + tf32-round (PV).
// ---------------------------------------------------------------------------
template <bool TRANS_B, int CAUSAL, int EPI>
__global__ void __launch_bounds__(128, 2)
gemm_tf32_kernel(const float* __restrict__ Ag, const float* __restrict__ Bg,
                 float* __restrict__ Cg, float* __restrict__ aux,
                 int K, int lda, int ldb, int ldc,
                 long long sA, long long sB, long long sC, float alpha)
{
    extern __shared__ float smem[];
    float* As = smem;                 // [2][A_BUF]
    float* Bs = smem + 2 * A_BUF;     // [2][B_BUF]

    const long long bz = blockIdx.z;
    const float* A  = Ag + bz * sA;
    const float* Bp = Bg + bz * sB;
    float*       Cp = Cg + bz * sC;

    const int m0 = blockIdx.y * BM;
    const int n0 = blockIdx.x * BN;

    if (CAUSAL == 1 && n0 > m0 + BM - 1) return;
    int kend = K;
    if (CAUSAL == 2) kend = min(K, m0 + BM);
    const int ntiles = kend / BK;

    const int tid  = threadIdx.x;
    const int warp = tid >> 5;
    const int lane = tid & 31;
    const int wm   = (warp >> 1) * 64;   // 2 warp rows of 64
    const int wn   = (warp & 1) * 64;    // 2 warp cols of 64

    wmma::fragment<wmma::accumulator, 16, 16, 8, float> acc[4][4];
    #pragma unroll
    for (int i = 0; i < 4; i++)
        #pragma unroll
        for (int j = 0; j < 4; j++)
            wmma::fill_fragment(acc[i][j], 0.0f);

    auto stage = [&](int kt, int b) {
        const int kbase = kt * BK;
        #pragma unroll
        for (int i = tid; i < (BM * BK) / 4; i += 128) {
            int r = i >> 3, c = (i & 7) * 4;
            cp16(smem_u32(&As[b * A_BUF + r * AS_STRIDE + c]),
                 &A[(size_t)(m0 + r) * lda + kbase + c]);
        }
        if constexpr (TRANS_B) {
            #pragma unroll
            for (int i = tid; i < (BN * BK) / 4; i += 128) {
                int r = i >> 3, c = (i & 7) * 4;
                cp16(smem_u32(&Bs[b * B_BUF + r * AS_STRIDE + c]),
                     &Bp[(size_t)(n0 + r) * ldb + kbase + c]);
            }
        } else {
            #pragma unroll
            for (int i = tid; i < (BK * BN) / 4; i += 128) {
                int r = i >> 5, c = (i & 31) * 4;
                cp16(smem_u32(&Bs[b * B_BUF + r * BN_STRIDE + c]),
                     &Bp[(size_t)(kbase + r) * ldb + n0 + c]);
            }
        }
    };

    stage(0, 0);
    cp_commit();

    using FragA = wmma::fragment<wmma::matrix_a, 16, 16, 8,
                                 wmma::precision::tf32, wmma::row_major>;

    for (int kt = 0; kt < ntiles; kt++) {
        const int buf = kt & 1;
        if (kt + 1 < ntiles) {
            stage(kt + 1, (kt + 1) & 1);
            cp_commit();
            cp_wait<1>();
        } else {
            cp_wait<0>();
        }
        __syncthreads();

        const float* Abase = &As[buf * A_BUF];
        const float* Bbase = &Bs[buf * B_BUF];

        #pragma unroll
        for (int kk = 0; kk < BK; kk += 8) {
            FragA af[4];
            #pragma unroll
            for (int im = 0; im < 4; im++)
                wmma::load_matrix_sync(af[im],
                    &Abase[(wm + im * 16) * AS_STRIDE + kk], AS_STRIDE);
            if constexpr (TRANS_B) {
                wmma::fragment<wmma::matrix_b, 16, 16, 8,
                               wmma::precision::tf32, wmma::col_major> bf[4];
                #pragma unroll
                for (int in = 0; in < 4; in++)
                    wmma::load_matrix_sync(bf[in],
                        &Bbase[(wn + in * 16) * AS_STRIDE + kk], AS_STRIDE);
                #pragma unroll
                for (int im = 0; im < 4; im++)
                    #pragma unroll
                    for (int in = 0; in < 4; in++)
                        wmma::mma_sync(acc[im][in], af[im], bf[in], acc[im][in]);
            } else {
                wmma::fragment<wmma::matrix_b, 16, 16, 8,
                               wmma::precision::tf32, wmma::row_major> bf[4];
                #pragma unroll
                for (int in = 0; in < 4; in++)
                    wmma::load_matrix_sync(bf[in],
                        &Bbase[kk * BN_STRIDE + wn + in * 16], BN_STRIDE);
                #pragma unroll
                for (int im = 0; im < 4; im++)
                    #pragma unroll
                    for (int in = 0; in < 4; in++)
                        wmma::mma_sync(acc[im][in], af[im], bf[in], acc[im][in]);
            }
        }
        __syncthreads();
    }

    // ---- alpha scale on fragments ----
    #pragma unroll
    for (int im = 0; im < 4; im++)
        #pragma unroll
        for (int in = 0; in < 4; in++)
            #pragma unroll
            for (int t = 0; t < acc[im][in].num_elements; t++)
                acc[im][in].x[t] *= alpha;

    if constexpr (EPI <= 1) {
        #pragma unroll
        for (int im = 0; im < 4; im++)
            #pragma unroll
            for (int in = 0; in < 4; in++) {
                if (EPI == 1) {
                    #pragma unroll
                    for (int t = 0; t < acc[im][in].num_elements; t++)
                        acc[im][in].x[t] = round_tf32(acc[im][in].x[t]);
                }
                wmma::store_matrix_sync(
                    &Cp[(size_t)(m0 + wm + im * 16) * ldc + n0 + wn + in * 16],
                    acc[im][in], ldc, wmma::mem_row_major);
            }
    } else {
        // Stage full 128x128 tile in smem (reuses staging buffers), sweep.
        float* stg = smem;   // 128 x STG_LD floats = 67584 B < 73728 B
        #pragma unroll
        for (int im = 0; im < 4; im++)
            #pragma unroll
            for (int in = 0; in < 4; in++)
                wmma::store_matrix_sync(
                    &stg[(wm + im * 16) * STG_LD + wn + in * 16],
                    acc[im][in], STG_LD, wmma::mem_row_major);
        __syncthreads();

        const int r0 = warp * 32;
        #pragma unroll 2
        for (int rr = 0; rr < 32; rr++) {
            const int r  = r0 + rr;
            const int gi = m0 + r;              // in-batch row (m0 < T)
            if constexpr (EPI == 2) {
                float s = 0.0f;
                #pragma unroll
                for (int cb = 0; cb < 4; cb++) {
                    const int j = n0 + cb * 32 + lane;
                    float v = stg[r * STG_LD + cb * 32 + lane];
                    float e = (j <= gi) ? __expf(v) : 0.0f;
                    e = round_tf32(e);
                    s += e;
                    Cp[(size_t)gi * ldc + j] = e;
                }
                #pragma unroll
                for (int o = 16; o; o >>= 1)
                    s += __shfl_xor_sync(0xFFFFFFFFu, s, o);
                if (lane == 0)
                    aux[(bz * T_ + gi) * NBLK + blockIdx.x] = s;
            } else {  // EPI == 3: row scale + round
                float sc = aux[bz * T_ + gi];
                #pragma unroll
                for (int cb = 0; cb < 4; cb++) {
                    float v = stg[r * STG_LD + cb * 32 + lane];
                    Cp[(size_t)gi * ldc + n0 + cb * 32 + lane] =
                        round_tf32(v * sc);
                }
            }
        }
    }
}

// ---------------------------------------------------------------------------
// Launch
// ---------------------------------------------------------------------------
extern "C" void kernel_launch(void* const* d_in, const int* in_sizes, int n_in,
                              void* d_out, int out_size)
{
    const float* x     = (const float*)d_in[0];   // [B, T, C]
    const float* Wqkv  = (const float*)d_in[1];   // [C, 3C]
    const float* Wproj = (const float*)d_in[2];   // [C, C]
    float* out = (float*)d_out;                   // [B, T, C]

    static float *xr = nullptr, *wq = nullptr, *wp = nullptr;
    static float *qkv = nullptr, *S = nullptr, *O = nullptr;
    static float *part = nullptr, *inv = nullptr;
    if (!qkv) {
        cudaGetSymbolAddress((void**)&xr,   g_x);
        cudaGetSymbolAddress((void**)&wq,   g_wq);
        cudaGetSymbolAddress((void**)&wp,   g_wp);
        cudaGetSymbolAddress((void**)&qkv,  g_qkv);
        cudaGetSymbolAddress((void**)&S,    g_S);
        cudaGetSymbolAddress((void**)&O,    g_O);
        cudaGetSymbolAddress((void**)&part, g_part);
        cudaGetSymbolAddress((void**)&inv,  g_inv);
        cudaFuncSetAttribute(gemm_tf32_kernel<false, 0, 1>,
            cudaFuncAttributeMaxDynamicSharedMemorySize, (int)SMEM_BYTES);
        cudaFuncSetAttribute(gemm_tf32_kernel<true, 1, 2>,
            cudaFuncAttributeMaxDynamicSharedMemorySize, (int)SMEM_BYTES);
        cudaFuncSetAttribute(gemm_tf32_kernel<false, 2, 3>,
            cudaFuncAttributeMaxDynamicSharedMemorySize, (int)SMEM_BYTES);
        cudaFuncSetAttribute(gemm_tf32_kernel<false, 0, 0>,
            cudaFuncAttributeMaxDynamicSharedMemorySize, (int)SMEM_BYTES);
    }

    const float scale = 1.0f / 32.0f;   // C^-0.5
    dim3 blk(128);

    // 0. pre-round operands to tf32
    {
        int n4x = (M_ROWS * C_) / 4;
        round_tf32_kernel<<<(n4x + 255) / 256, 256>>>(x, xr, n4x);
        int n4q = (C_ * N_QKV) / 4;
        round_tf32_kernel<<<(n4q + 255) / 256, 256>>>(Wqkv, wq, n4q);
        int n4p = (C_ * C_) / 4;
        round_tf32_kernel<<<(n4p + 255) / 256, 256>>>(Wproj, wp, n4p);
    }

    // 1. qkv = x @ Wqkv (tf32-rounded output)
    gemm_tf32_kernel<false, 0, 1>
        <<<dim3(N_QKV / BN, M_ROWS / BM, 1), blk, SMEM_BYTES>>>(
        xr, wq, qkv, nullptr, C_, C_, N_QKV, N_QKV, 0, 0, 0, 1.0f);

    // 2. E_b = exp(scale * Q_b @ K_b^T) causal-masked; partial row sums.
    gemm_tf32_kernel<true, 1, 2>
        <<<dim3(T_ / BN, T_ / BM, B_), blk, SMEM_BYTES>>>(
        qkv, qkv + C_, S, part, C_, N_QKV, N_QKV, T_,
        (long long)T_ * N_QKV, (long long)T_ * N_QKV, (long long)T_ * T_,
        scale);

    // 3. inv[row] = 1 / rowsum
    inv_rowsum_kernel<<<(M_ROWS + 255) / 256, 256>>>(part, inv);

    // 4. O_b = diag(inv) * E_b @ V_b (K-limited; row-scaled, rounded)
    gemm_tf32_kernel<false, 2, 3>
        <<<dim3(C_ / BN, T_ / BM, B_), blk, SMEM_BYTES>>>(
        S, qkv + 2 * C_, O, inv, T_, T_, N_QKV, C_,
        (long long)T_ * T_, (long long)T_ * N_QKV, (long long)T_ * C_,
        1.0f);

    // 5. out = O @ Wproj (final fp32)
    gemm_tf32_kernel<false, 0, 0>
        <<<dim3(C_ / BN, M_ROWS / BM, 1), blk, SMEM_BYTES>>>(
        O, wp, out, nullptr, C_, C_, C_, C_, 0, 0, 0, 1.0f);
}

// round 9
// speedup vs baseline: 1.2033x; 1.0012x over previous
#include <cuda_runtime.h>
#include <cuda_bf16.h>
#include <mma.h>
#include <math.h>

using namespace nvcuda;

// Problem constants
constexpr int B_ = 8;
constexpr int T_ = 2048;
constexpr int C_ = 1024;
constexpr int M_ROWS = B_ * T_;      // 16384
constexpr int N_QKV  = 3 * C_;       // 3072
constexpr int NBLK   = T_ / 128;     // 16 col-blocks per row for partial sums

// GEMM tiling: 128x128 CTA tile, 4 warps (2Mx2N), warp tile 64x64, BK=32
constexpr int BM = 128;
constexpr int BN = 128;
constexpr int BK = 32;
constexpr int AS_STRIDE = BK + 4;    // 36
constexpr int BN_STRIDE = BN + 4;    // 132
constexpr int A_BUF = BM * AS_STRIDE;               // 4608 floats
constexpr int B_BUF = BM * AS_STRIDE;               // 4608 (>= 32*132=4224)
constexpr size_t SMEM_BYTES = (size_t)(2 * A_BUF + 2 * B_BUF) * 4;  // 73728
constexpr int STG_LD = BN + 4;       // 132, stage stride

// Scratch (device globals)
__device__ float g_x[(size_t)M_ROWS * C_];
__device__ float g_wq[(size_t)C_ * N_QKV];
__device__ float g_wp[(size_t)C_ * C_];
__device__ float g_qkv[(size_t)M_ROWS * N_QKV];
__device__ float g_S[(size_t)B_ * T_ * T_];
__device__ float g_O[(size_t)M_ROWS * C_];
__device__ float g_part[(size_t)M_ROWS * NBLK];   // per (row, colblock) sums
__device__ float g_inv[(size_t)M_ROWS];           // 1 / rowsum

__device__ __forceinline__ unsigned smem_u32(const void* p) {
    return (unsigned)__cvta_generic_to_shared(p);
}
__device__ __forceinline__ void cp16(unsigned s, const void* g) {
    asm volatile("cp.async.cg.shared.global [%0], [%1], 16;\n" :: "r"(s), "l"(g));
}
__device__ __forceinline__ void cp_commit() {
    asm volatile("cp.async.commit_group;\n" ::: "memory");
}
template <int N>
__device__ __forceinline__ void cp_wait() {
    asm volatile("cp.async.wait_group %0;\n" :: "n"(N) : "memory");
}
__device__ __forceinline__ float round_tf32(float v) {
    return wmma::__float_to_tf32(v);
}

// ---------------------------------------------------------------------------
__global__ void __launch_bounds__(256)
round_tf32_kernel(const float* __restrict__ in, float* __restrict__ out, int n4)
{
    int i = blockIdx.x * blockDim.x + threadIdx.x;
    if (i >= n4) return;
    float4 v = ((const float4*)in)[i];
    v.x = round_tf32(v.x); v.y = round_tf32(v.y);
    v.z = round_tf32(v.z); v.w = round_tf32(v.w);
    ((float4*)out)[i] = v;
}

// Deterministic row-sum inversion: inv[g] = 1 / sum_{bx<=i/128} part[g][bx]
__global__ void __launch_bounds__(256)
inv_rowsum_kernel(const float* __restrict__ part, float* __restrict__ inv)
{
    int g = blockIdx.x * blockDim.x + threadIdx.x;
    if (g >= M_ROWS) return;
    int i = g % T_;
    int nb = (i >> 7) + 1;
    float s = 0.0f;
    for (int b = 0; b < nb; b++) s += part[(size_t)g * NBLK + b];
    inv[g] = 1.0f / s;
}

// ---------------------------------------------------------------------------
// tf32 WMMA GEMM, 128x128x32 tile, 128 threads (4 warps, warp tile 64x64),
// cp.async double-buffered staging. Operands pre-rounded to tf32.
// TRANS_B: B is [N,K] (A@B^T) else [K,N] (A@B).
// CAUSAL: 0 none; 1 skip blocks above diagonal; 2 K-limit to m0+BM.
// EPI: 0 plain; 1 tf32-round; 2 exp+causal-mask+rowsum-partials (QK);
//      3 row-scale by aux[row] + tf32-round (PV).
// ---------------------------------------------------------------------------
template <bool TRANS_B, int CAUSAL, int EPI>
__global__ void __launch_bounds__(128, 2)
gemm_tf32_kernel(const float* __restrict__ Ag, const float* __restrict__ Bg,
                 float* __restrict__ Cg, float* __restrict__ aux,
                 int K, int lda, int ldb, int ldc,
                 long long sA, long long sB, long long sC, float alpha)
{
    extern __shared__ float smem[];
    float* As = smem;                 // [2][A_BUF]
    float* Bs = smem + 2 * A_BUF;     // [2][B_BUF]

    const long long bz = blockIdx.z;
    const float* A  = Ag + bz * sA;
    const float* Bp = Bg + bz * sB;
    float*       Cp = Cg + bz * sC;

    const int m0 = blockIdx.y * BM;
    const int n0 = blockIdx.x * BN;

    if (CAUSAL == 1 && n0 > m0 + BM - 1) return;
    int kend = K;
    if (CAUSAL == 2) kend = min(K, m0 + BM);
    const int ntiles = kend / BK;

    const int tid  = threadIdx.x;
    const int warp = tid >> 5;
    const int lane = tid & 31;
    const int wm   = (warp >> 1) * 64;   // 2 warp rows of 64
    const int wn   = (warp & 1) * 64;    // 2 warp cols of 64

    wmma::fragment<wmma::accumulator, 16, 16, 8, float> acc[4][4];
    #pragma unroll
    for (int i = 0; i < 4; i++)
        #pragma unroll
        for (int j = 0; j < 4; j++)
            wmma::fill_fragment(acc[i][j], 0.0f);

    auto stage = [&](int kt, int b) {
        const int kbase = kt * BK;
        #pragma unroll
        for (int i = tid; i < (BM * BK) / 4; i += 128) {
            int r = i >> 3, c = (i & 7) * 4;
            cp16(smem_u32(&As[b * A_BUF + r * AS_STRIDE + c]),
                 &A[(size_t)(m0 + r) * lda + kbase + c]);
        }
        if constexpr (TRANS_B) {
            #pragma unroll
            for (int i = tid; i < (BN * BK) / 4; i += 128) {
                int r = i >> 3, c = (i & 7) * 4;
                cp16(smem_u32(&Bs[b * B_BUF + r * AS_STRIDE + c]),
                     &Bp[(size_t)(n0 + r) * ldb + kbase + c]);
            }
        } else {
            #pragma unroll
            for (int i = tid; i < (BK * BN) / 4; i += 128) {
                int r = i >> 5, c = (i & 31) * 4;
                cp16(smem_u32(&Bs[b * B_BUF + r * BN_STRIDE + c]),
                     &Bp[(size_t)(kbase + r) * ldb + n0 + c]);
            }
        }
    };

    stage(0, 0);
    cp_commit();

    using FragA = wmma::fragment<wmma::matrix_a, 16, 16, 8,
                                 wmma::precision::tf32, wmma::row_major>;

    for (int kt = 0; kt < ntiles; kt++) {
        const int buf = kt & 1;
        if (kt + 1 < ntiles) {
            stage(kt + 1, (kt + 1) & 1);
            cp_commit();
            cp_wait<1>();
        } else {
            cp_wait<0>();
        }
        __syncthreads();

        const float* Abase = &As[buf * A_BUF];
        const float* Bbase = &Bs[buf * B_BUF];

        #pragma unroll
        for (int kk = 0; kk < BK; kk += 8) {
            FragA af[4];
            #pragma unroll
            for (int im = 0; im < 4; im++)
                wmma::load_matrix_sync(af[im],
                    &Abase[(wm + im * 16) * AS_STRIDE + kk], AS_STRIDE);
            if constexpr (TRANS_B) {
                wmma::fragment<wmma::matrix_b, 16, 16, 8,
                               wmma::precision::tf32, wmma::col_major> bf[4];
                #pragma unroll
                for (int in = 0; in < 4; in++)
                    wmma::load_matrix_sync(bf[in],
                        &Bbase[(wn + in * 16) * AS_STRIDE + kk], AS_STRIDE);
                #pragma unroll
                for (int im = 0; im < 4; im++)
                    #pragma unroll
                    for (int in = 0; in < 4; in++)
                        wmma::mma_sync(acc[im][in], af[im], bf[in], acc[im][in]);
            } else {
                wmma::fragment<wmma::matrix_b, 16, 16, 8,
                               wmma::precision::tf32, wmma::row_major> bf[4];
                #pragma unroll
                for (int in = 0; in < 4; in++)
                    wmma::load_matrix_sync(bf[in],
                        &Bbase[kk * BN_STRIDE + wn + in * 16], BN_STRIDE);
                #pragma unroll
                for (int im = 0; im < 4; im++)
                    #pragma unroll
                    for (int in = 0; in < 4; in++)
                        wmma::mma_sync(acc[im][in], af[im], bf[in], acc[im][in]);
            }
        }
        __syncthreads();
    }

    // ---- alpha scale on fragments ----
    #pragma unroll
    for (int im = 0; im < 4; im++)
        #pragma unroll
        for (int in = 0; in < 4; in++)
            #pragma unroll
            for (int t = 0; t < acc[im][in].num_elements; t++)
                acc[im][in].x[t] *= alpha;

    if constexpr (EPI <= 1) {
        #pragma unroll
        for (int im = 0; im < 4; im++)
            #pragma unroll
            for (int in = 0; in < 4; in++) {
                if (EPI == 1) {
                    #pragma unroll
                    for (int t = 0; t < acc[im][in].num_elements; t++)
                        acc[im][in].x[t] = round_tf32(acc[im][in].x[t]);
                }
                wmma::store_matrix_sync(
                    &Cp[(size_t)(m0 + wm + im * 16) * ldc + n0 + wn + in * 16],
                    acc[im][in], ldc, wmma::mem_row_major);
            }
    } else {
        // Stage full 128x128 tile in smem (reuses staging buffers), sweep.
        float* stg = smem;   // 128 x STG_LD floats = 67584 B < 73728 B
        #pragma unroll
        for (int im = 0; im < 4; im++)
            #pragma unroll
            for (int in = 0; in < 4; in++)
                wmma::store_matrix_sync(
                    &stg[(wm + im * 16) * STG_LD + wn + in * 16],
                    acc[im][in], STG_LD, wmma::mem_row_major);
        __syncthreads();

        const int r0 = warp * 32;
        #pragma unroll 2
        for (int rr = 0; rr < 32; rr++) {
            const int r  = r0 + rr;
            const int gi = m0 + r;              // in-batch row (m0 < T)
            if constexpr (EPI == 2) {
                float s = 0.0f;
                #pragma unroll
                for (int cb = 0; cb < 4; cb++) {
                    const int j = n0 + cb * 32 + lane;
                    float v = stg[r * STG_LD + cb * 32 + lane];
                    float e = (j <= gi) ? __expf(v) : 0.0f;
                    e = round_tf32(e);
                    s += e;
                    Cp[(size_t)gi * ldc + j] = e;
                }
                #pragma unroll
                for (int o = 16; o; o >>= 1)
                    s += __shfl_xor_sync(0xFFFFFFFFu, s, o);
                if (lane == 0)
                    aux[(bz * T_ + gi) * NBLK + blockIdx.x] = s;
            } else {  // EPI == 3: row scale + round
                float sc = aux[bz * T_ + gi];
                #pragma unroll
                for (int cb = 0; cb < 4; cb++) {
                    float v = stg[r * STG_LD + cb * 32 + lane];
                    Cp[(size_t)gi * ldc + n0 + cb * 32 + lane] =
                        round_tf32(v * sc);
                }
            }
        }
    }
}

// ---------------------------------------------------------------------------
// Launch
// ---------------------------------------------------------------------------
extern "C" void kernel_launch(void* const* d_in, const int* in_sizes, int n_in,
                              void* d_out, int out_size)
{
    const float* x     = (const float*)d_in[0];   // [B, T, C]
    const float* Wqkv  = (const float*)d_in[1];   // [C, 3C]
    const float* Wproj = (const float*)d_in[2];   // [C, C]
    float* out = (float*)d_out;                   // [B, T, C]

    static float *xr = nullptr, *wq = nullptr, *wp = nullptr;
    static float *qkv = nullptr, *S = nullptr, *O = nullptr;
    static float *part = nullptr, *inv = nullptr;
    if (!qkv) {
        cudaGetSymbolAddress((void**)&xr,   g_x);
        cudaGetSymbolAddress((void**)&wq,   g_wq);
        cudaGetSymbolAddress((void**)&wp,   g_wp);
        cudaGetSymbolAddress((void**)&qkv,  g_qkv);
        cudaGetSymbolAddress((void**)&S,    g_S);
        cudaGetSymbolAddress((void**)&O,    g_O);
        cudaGetSymbolAddress((void**)&part, g_part);
        cudaGetSymbolAddress((void**)&inv,  g_inv);
        cudaFuncSetAttribute(gemm_tf32_kernel<false, 0, 1>,
            cudaFuncAttributeMaxDynamicSharedMemorySize, (int)SMEM_BYTES);
        cudaFuncSetAttribute(gemm_tf32_kernel<true, 1, 2>,
            cudaFuncAttributeMaxDynamicSharedMemorySize, (int)SMEM_BYTES);
        cudaFuncSetAttribute(gemm_tf32_kernel<false, 2, 3>,
            cudaFuncAttributeMaxDynamicSharedMemorySize, (int)SMEM_BYTES);
        cudaFuncSetAttribute(gemm_tf32_kernel<false, 0, 0>,
            cudaFuncAttributeMaxDynamicSharedMemorySize, (int)SMEM_BYTES);
    }

    const float scale = 1.0f / 32.0f;   // C^-0.5
    dim3 blk(128);

    // 0. pre-round operands to tf32
    {
        int n4x = (M_ROWS * C_) / 4;
        round_tf32_kernel<<<(n4x + 255) / 256, 256>>>(x, xr, n4x);
        int n4q = (C_ * N_QKV) / 4;
        round_tf32_kernel<<<(n4q + 255) / 256, 256>>>(Wqkv, wq, n4q);
        int n4p = (C_ * C_) / 4;
        round_tf32_kernel<<<(n4p + 255) / 256, 256>>>(Wproj, wp, n4p);
    }

    // 1. qkv = x @ Wqkv (tf32-rounded output)
    gemm_tf32_kernel<false, 0, 1>
        <<<dim3(N_QKV / BN, M_ROWS / BM, 1), blk, SMEM_BYTES>>>(
        xr, wq, qkv, nullptr, C_, C_, N_QKV, N_QKV, 0, 0, 0, 1.0f);

    // 2. E_b = exp(scale * Q_b @ K_b^T) causal-masked; partial row sums.
    gemm_tf32_kernel<true, 1, 2>
        <<<dim3(T_ / BN, T_ / BM, B_), blk, SMEM_BYTES>>>(
        qkv, qkv + C_, S, part, C_, N_QKV, N_QKV, T_,
        (long long)T_ * N_QKV, (long long)T_ * N_QKV, (long long)T_ * T_,
        scale);

    // 3. inv[row] = 1 / rowsum
    inv_rowsum_kernel<<<(M_ROWS + 255) / 256, 256>>>(part, inv);

    // 4. O_b = diag(inv) * E_b @ V_b (K-limited; row-scaled, rounded)
    gemm_tf32_kernel<false, 2, 3>
        <<<dim3(C_ / BN, T_ / BM, B_), blk, SMEM_BYTES>>>(
        S, qkv + 2 * C_, O, inv, T_, T_, N_QKV, C_,
        (long long)T_ * T_, (long long)T_ * N_QKV, (long long)T_ * C_,
        1.0f);

    // 5. out = O @ Wproj (final fp32)
    gemm_tf32_kernel<false, 0, 0>
        <<<dim3(C_ / BN, M_ROWS / BM, 1), blk, SMEM_BYTES>>>(
        O, wp, out, nullptr, C_, C_, C_, C_, 0, 0, 0, 1.0f);
}

// round 10
// speedup vs baseline: 5.0183x; 4.1706x over previous
#include <cuda_runtime.h>
#include <cuda_fp16.h>
#include <mma.h>
#include <math.h>

using namespace nvcuda;

// Problem constants
constexpr int B_ = 8;
constexpr int T_ = 2048;
constexpr int C_ = 1024;
constexpr int M_ROWS = B_ * T_;      // 16384
constexpr int N_QKV  = 3 * C_;       // 3072
constexpr int NBLK   = T_ / 128;     // 16 col-blocks per row for partial sums

// GEMM tiling: 128x128 CTA tile, 4 warps (2Mx2N), warp tile 64x64, BK=32
constexpr int BM = 128;
constexpr int BN = 128;
constexpr int BK = 32;               // 32 halves = 64B per row
constexpr int AS_STRIDE = BK + 16;   // 48 halves (96B rows, 16B aligned)
constexpr int BN_STRIDE = BN + 8;    // 136 halves (272B rows, 16B aligned)
constexpr int A_BUF = BM * AS_STRIDE;   // 6144 halves
constexpr int B_BUF = BM * AS_STRIDE;   // 6144 (>= 32*136=4352)
constexpr size_t SMEM_BYTES = 73728;    // covers GEMM (48KB) + epi staging (66KB)
constexpr int STG_LD = BN + 4;          // 132 floats, epi staging stride

// Scratch (device globals)
__device__ __half g_xh[(size_t)M_ROWS * C_];
__device__ __half g_wqh[(size_t)C_ * N_QKV];
__device__ __half g_wph[(size_t)C_ * C_];
__device__ __half g_qkv[(size_t)M_ROWS * N_QKV];   // [B*T, 3C]
__device__ __half g_S[(size_t)B_ * T_ * T_];       // E = exp(scores)
__device__ __half g_O[(size_t)M_ROWS * C_];
__device__ float  g_part[(size_t)M_ROWS * NBLK];
__device__ float  g_inv[(size_t)M_ROWS];

__device__ __forceinline__ unsigned smem_u32(const void* p) {
    return (unsigned)__cvta_generic_to_shared(p);
}
__device__ __forceinline__ void cp16(unsigned s, const void* g) {
    asm volatile("cp.async.cg.shared.global [%0], [%1], 16;\n" :: "r"(s), "l"(g));
}
__device__ __forceinline__ void cp_commit() {
    asm volatile("cp.async.commit_group;\n" ::: "memory");
}
template <int N>
__device__ __forceinline__ void cp_wait() {
    asm volatile("cp.async.wait_group %0;\n" :: "n"(N) : "memory");
}

// ---------------------------------------------------------------------------
// fp32 -> fp16 conversion, 8 elements per thread (16B stores)
// ---------------------------------------------------------------------------
__global__ void __launch_bounds__(256)
f2h_kernel(const float* __restrict__ in, __half* __restrict__ out, int n8)
{
    int i = blockIdx.x * blockDim.x + threadIdx.x;
    if (i >= n8) return;
    float4 a = ((const float4*)in)[2 * i];
    float4 b = ((const float4*)in)[2 * i + 1];
    __half2 h0 = __floats2half2_rn(a.x, a.y);
    __half2 h1 = __floats2half2_rn(a.z, a.w);
    __half2 h2 = __floats2half2_rn(b.x, b.y);
    __half2 h3 = __floats2half2_rn(b.z, b.w);
    uint4 u;
    u.x = *reinterpret_cast<unsigned*>(&h0);
    u.y = *reinterpret_cast<unsigned*>(&h1);
    u.z = *reinterpret_cast<unsigned*>(&h2);
    u.w = *reinterpret_cast<unsigned*>(&h3);
    ((uint4*)out)[i] = u;
}

// Deterministic row-sum inversion: inv[g] = 1 / sum_{bx<=i/128} part[g][bx]
__global__ void __launch_bounds__(256)
inv_rowsum_kernel(const float* __restrict__ part, float* __restrict__ inv)
{
    int g = blockIdx.x * blockDim.x + threadIdx.x;
    if (g >= M_ROWS) return;
    int i = g % T_;
    int nb = (i >> 7) + 1;
    float s = 0.0f;
    for (int b = 0; b < nb; b++) s += part[(size_t)g * NBLK + b];
    inv[g] = 1.0f / s;
}

// ---------------------------------------------------------------------------
// fp16 WMMA GEMM (fp32 accum), 128x128x32 tile, 128 threads (4 warps,
// warp tile 64x64, m16n16k16), cp.async double-buffered staging.
// TRANS_B: B is [N,K] (A@B^T) else [K,N] (A@B).
// CAUSAL: 0 none; 1 skip blocks above diagonal; 2 K-limit to m0+BM.
// EPI: 0 fp32 store (final); 1 fp16 store; 2 exp+mask+rowsum-partials (fp16);
//      3 row-scale by aux[row] (fp16).
// ---------------------------------------------------------------------------
template <bool TRANS_B, int CAUSAL, int EPI>
__global__ void __launch_bounds__(128, 2)
gemm_fp16_kernel(const __half* __restrict__ Ag, const __half* __restrict__ Bg,
                 void* __restrict__ Cgv, float* __restrict__ aux,
                 int K, int lda, int ldb, int ldc,
                 long long sA, long long sB, long long sC, float alpha)
{
    extern __shared__ char smem_raw[];
    __half* As = (__half*)smem_raw;                // [2][A_BUF]
    __half* Bs = (__half*)smem_raw + 2 * A_BUF;    // [2][B_BUF]

    const long long bz = blockIdx.z;
    const __half* A  = Ag + bz * sA;
    const __half* Bp = Bg + bz * sB;

    const int m0 = blockIdx.y * BM;
    const int n0 = blockIdx.x * BN;

    if (CAUSAL == 1 && n0 > m0 + BM - 1) return;
    int kend = K;
    if (CAUSAL == 2) kend = min(K, m0 + BM);
    const int ntiles = kend / BK;

    const int tid  = threadIdx.x;
    const int warp = tid >> 5;
    const int lane = tid & 31;
    const int wm   = (warp >> 1) * 64;
    const int wn   = (warp & 1) * 64;

    wmma::fragment<wmma::accumulator, 16, 16, 16, float> acc[4][4];
    #pragma unroll
    for (int i = 0; i < 4; i++)
        #pragma unroll
        for (int j = 0; j < 4; j++)
            wmma::fill_fragment(acc[i][j], 0.0f);

    auto stage = [&](int kt, int b) {
        const int kbase = kt * BK;
        // A tile 128x32 halves: 512 16B-chunks (8 halves each), 4/thread
        #pragma unroll
        for (int i = tid; i < (BM * BK) / 8; i += 128) {
            int r = i >> 2, c = (i & 3) * 8;
            cp16(smem_u32(&As[b * A_BUF + r * AS_STRIDE + c]),
                 &A[(size_t)(m0 + r) * lda + kbase + c]);
        }
        if constexpr (TRANS_B) {
            #pragma unroll
            for (int i = tid; i < (BN * BK) / 8; i += 128) {
                int r = i >> 2, c = (i & 3) * 8;
                cp16(smem_u32(&Bs[b * B_BUF + r * AS_STRIDE + c]),
                     &Bp[(size_t)(n0 + r) * ldb + kbase + c]);
            }
        } else {
            // B tile 32x128 halves: 512 chunks
            #pragma unroll
            for (int i = tid; i < (BK * BN) / 8; i += 128) {
                int r = i >> 4, c = (i & 15) * 8;
                cp16(smem_u32(&Bs[b * B_BUF + r * BN_STRIDE + c]),
                     &Bp[(size_t)(kbase + r) * ldb + n0 + c]);
            }
        }
    };

    stage(0, 0);
    cp_commit();

    using FragA = wmma::fragment<wmma::matrix_a, 16, 16, 16, __half,
                                 wmma::row_major>;

    for (int kt = 0; kt < ntiles; kt++) {
        const int buf = kt & 1;
        if (kt + 1 < ntiles) {
            stage(kt + 1, (kt + 1) & 1);
            cp_commit();
            cp_wait<1>();
        } else {
            cp_wait<0>();
        }
        __syncthreads();

        const __half* Abase = &As[buf * A_BUF];
        const __half* Bbase = &Bs[buf * B_BUF];

        #pragma unroll
        for (int kk = 0; kk < BK; kk += 16) {
            FragA af[4];
            #pragma unroll
            for (int im = 0; im < 4; im++)
                wmma::load_matrix_sync(af[im],
                    &Abase[(wm + im * 16) * AS_STRIDE + kk], AS_STRIDE);
            if constexpr (TRANS_B) {
                wmma::fragment<wmma::matrix_b, 16, 16, 16, __half,
                               wmma::col_major> bf[4];
                #pragma unroll
                for (int in = 0; in < 4; in++)
                    wmma::load_matrix_sync(bf[in],
                        &Bbase[(wn + in * 16) * AS_STRIDE + kk], AS_STRIDE);
                #pragma unroll
                for (int im = 0; im < 4; im++)
                    #pragma unroll
                    for (int in = 0; in < 4; in++)
                        wmma::mma_sync(acc[im][in], af[im], bf[in], acc[im][in]);
            } else {
                wmma::fragment<wmma::matrix_b, 16, 16, 16, __half,
                               wmma::row_major> bf[4];
                #pragma unroll
                for (int in = 0; in < 4; in++)
                    wmma::load_matrix_sync(bf[in],
                        &Bbase[kk * BN_STRIDE + wn + in * 16], BN_STRIDE);
                #pragma unroll
                for (int im = 0; im < 4; im++)
                    #pragma unroll
                    for (int in = 0; in < 4; in++)
                        wmma::mma_sync(acc[im][in], af[im], bf[in], acc[im][in]);
            }
        }
        __syncthreads();
    }

    // ---- alpha scale ----
    #pragma unroll
    for (int im = 0; im < 4; im++)
        #pragma unroll
        for (int in = 0; in < 4; in++)
            #pragma unroll
            for (int t = 0; t < acc[im][in].num_elements; t++)
                acc[im][in].x[t] *= alpha;

    if constexpr (EPI == 0) {
        float* Cp = (float*)Cgv + bz * sC;
        #pragma unroll
        for (int im = 0; im < 4; im++)
            #pragma unroll
            for (int in = 0; in < 4; in++)
                wmma::store_matrix_sync(
                    &Cp[(size_t)(m0 + wm + im * 16) * ldc + n0 + wn + in * 16],
                    acc[im][in], ldc, wmma::mem_row_major);
    } else {
        __half* Cp = (__half*)Cgv + bz * sC;
        // Stage full 128x128 fp32 tile in smem, then half2 sweep.
        float* stg = (float*)smem_raw;   // 128 x 132 floats = 67584 B
        #pragma unroll
        for (int im = 0; im < 4; im++)
            #pragma unroll
            for (int in = 0; in < 4; in++)
                wmma::store_matrix_sync(
                    &stg[(wm + im * 16) * STG_LD + wn + in * 16],
                    acc[im][in], STG_LD, wmma::mem_row_major);
        __syncthreads();

        const int r0 = warp * 32;
        #pragma unroll 2
        for (int rr = 0; rr < 32; rr++) {
            const int r  = r0 + rr;
            const int gi = m0 + r;              // in-batch row (m0 < T)
            if constexpr (EPI == 2) {
                float s = 0.0f;
                #pragma unroll
                for (int cb = 0; cb < 2; cb++) {
                    const int c  = cb * 64 + lane * 2;
                    const int j0 = n0 + c;
                    float v0 = stg[r * STG_LD + c];
                    float v1 = stg[r * STG_LD + c + 1];
                    float e0 = (j0     <= gi) ? __expf(v0) : 0.0f;
                    float e1 = (j0 + 1 <= gi) ? __expf(v1) : 0.0f;
                    __half2 h = __floats2half2_rn(e0, e1);
                    s += __low2float(h) + __high2float(h);
                    *(__half2*)&Cp[(size_t)gi * ldc + j0] = h;
                }
                #pragma unroll
                for (int o = 16; o; o >>= 1)
                    s += __shfl_xor_sync(0xFFFFFFFFu, s, o);
                if (lane == 0)
                    aux[(bz * T_ + gi) * NBLK + blockIdx.x] = s;
            } else if constexpr (EPI == 3) {
                float sc = aux[bz * T_ + gi];
                #pragma unroll
                for (int cb = 0; cb < 2; cb++) {
                    const int c = cb * 64 + lane * 2;
                    float v0 = stg[r * STG_LD + c] * sc;
                    float v1 = stg[r * STG_LD + c + 1] * sc;
                    *(__half2*)&Cp[(size_t)gi * ldc + n0 + c] =
                        __floats2half2_rn(v0, v1);
                }
            } else {  // EPI == 1: plain fp16 store
                #pragma unroll
                for (int cb = 0; cb < 2; cb++) {
                    const int c = cb * 64 + lane * 2;
                    float v0 = stg[r * STG_LD + c];
                    float v1 = stg[r * STG_LD + c + 1];
                    *(__half2*)&Cp[(size_t)gi * ldc + n0 + c] =
                        __floats2half2_rn(v0, v1);
                }
            }
        }
    }
}

// ---------------------------------------------------------------------------
// Launch
// ---------------------------------------------------------------------------
extern "C" void kernel_launch(void* const* d_in, const int* in_sizes, int n_in,
                              void* d_out, int out_size)
{
    const float* x     = (const float*)d_in[0];   // [B, T, C]
    const float* Wqkv  = (const float*)d_in[1];   // [C, 3C]
    const float* Wproj = (const float*)d_in[2];   // [C, C]
    float* out = (float*)d_out;                   // [B, T, C]

    static __half *xh = nullptr, *wqh = nullptr, *wph = nullptr;
    static __half *qkv = nullptr, *S = nullptr, *O = nullptr;
    static float *part = nullptr, *inv = nullptr;
    if (!qkv) {
        cudaGetSymbolAddress((void**)&xh,   g_xh);
        cudaGetSymbolAddress((void**)&wqh,  g_wqh);
        cudaGetSymbolAddress((void**)&wph,  g_wph);
        cudaGetSymbolAddress((void**)&qkv,  g_qkv);
        cudaGetSymbolAddress((void**)&S,    g_S);
        cudaGetSymbolAddress((void**)&O,    g_O);
        cudaGetSymbolAddress((void**)&part, g_part);
        cudaGetSymbolAddress((void**)&inv,  g_inv);
        cudaFuncSetAttribute(gemm_fp16_kernel<false, 0, 1>,
            cudaFuncAttributeMaxDynamicSharedMemorySize, (int)SMEM_BYTES);
        cudaFuncSetAttribute(gemm_fp16_kernel<true, 1, 2>,
            cudaFuncAttributeMaxDynamicSharedMemorySize, (int)SMEM_BYTES);
        cudaFuncSetAttribute(gemm_fp16_kernel<false, 2, 3>,
            cudaFuncAttributeMaxDynamicSharedMemorySize, (int)SMEM_BYTES);
        cudaFuncSetAttribute(gemm_fp16_kernel<false, 0, 0>,
            cudaFuncAttributeMaxDynamicSharedMemorySize, (int)SMEM_BYTES);
    }

    const float scale = 1.0f / 32.0f;   // C^-0.5
    dim3 blk(128);

    // 0. convert inputs to fp16
    f2h_kernel<<<(M_ROWS * C_ / 8 + 255) / 256, 256>>>(x, xh, M_ROWS * C_ / 8);
    f2h_kernel<<<(C_ * N_QKV / 8 + 255) / 256, 256>>>(Wqkv, wqh, C_ * N_QKV / 8);
    f2h_kernel<<<(C_ * C_ / 8 + 255) / 256, 256>>>(Wproj, wph, C_ * C_ / 8);

    // 1. qkv = x @ Wqkv (fp16 out)
    gemm_fp16_kernel<false, 0, 1>
        <<<dim3(N_QKV / BN, M_ROWS / BM, 1), blk, SMEM_BYTES>>>(
        xh, wqh, qkv, nullptr, C_, C_, N_QKV, N_QKV, 0, 0, 0, 1.0f);

    // 2. E_b = exp(scale * Q_b @ K_b^T) causal-masked; partial row sums.
    gemm_fp16_kernel<true, 1, 2>
        <<<dim3(T_ / BN, T_ / BM, B_), blk, SMEM_BYTES>>>(
        qkv, qkv + C_, S, part, C_, N_QKV, N_QKV, T_,
        (long long)T_ * N_QKV, (long long)T_ * N_QKV, (long long)T_ * T_,
        scale);

    // 3. inv[row] = 1 / rowsum
    inv_rowsum_kernel<<<(M_ROWS + 255) / 256, 256>>>(part, inv);

    // 4. O_b = diag(inv) * E_b @ V_b (K-limited; fp16 out)
    gemm_fp16_kernel<false, 2, 3>
        <<<dim3(C_ / BN, T_ / BM, B_), blk, SMEM_BYTES>>>(
        S, qkv + 2 * C_, O, inv, T_, T_, N_QKV, C_,
        (long long)T_ * T_, (long long)T_ * N_QKV, (long long)T_ * C_,
        1.0f);

    // 5. out = O @ Wproj (fp32 final)
    gemm_fp16_kernel<false, 0, 0>
        <<<dim3(C_ / BN, M_ROWS / BM, 1), blk, SMEM_BYTES>>>(
        O, wph, out, nullptr, C_, C_, C_, C_, 0, 0, 0, 1.0f);
}